// round 1
// baseline (speedup 1.0000x reference)
#include <cuda_runtime.h>
#include <cuda_bf16.h>

// Problem constants
#define NBATCH 4
#define NSEQ   2048
#define NDIMS  1024
#define NHEADS 16
#define HD     64         // head dim
#define NROT   32         // HD/2
#define NROWS  (NBATCH*NSEQ*NHEADS)   // 131072

// Scratch (allocation-free rule: __device__ globals)
__device__ __align__(16) float g_M[HD * HD];          // combined Givens-chain @ r_matrix
__device__ __align__(16) float g_sin[NSEQ * NROT];    // sin(pos * inv_freq[n])
__device__ __align__(16) float g_cos[NSEQ * NROT];

// ---------------------------------------------------------------------------
// Setup kernel 1: build M = T0 * T1 * ... * T31 * R   (so that row @ M == scan+matmul)
// Left-multiplying by T_k transforms ROWS i,j of the accumulator:
//   row_i' = c*row_i - s*row_j ; row_j' = s*row_i + c*row_j   (i != j)
//   row_i' = s*row_i                                          (i == j)
// Apply in REVERSE k order starting from R.
// ---------------------------------------------------------------------------
__global__ void build_M_kernel(const float* __restrict__ thetas,
                               const float* __restrict__ tscale,
                               const float* __restrict__ R,
                               const int*   __restrict__ pairs) {
    __shared__ float Ms[HD * HD];
    const int t = threadIdx.x;  // 0..63, owns column t
    for (int d = 0; d < HD; d++) Ms[d * HD + t] = R[d * HD + t];
    __syncthreads();
    const float ts = tscale[0];
    for (int k = NROT - 1; k >= 0; k--) {
        const int i = pairs[2 * k];
        const int j = pairs[2 * k + 1];
        const float th = thetas[k] * ts;
        const float c = cosf(th);
        const float s = sinf(th);
        const float a = Ms[i * HD + t];
        const float b = Ms[j * HD + t];
        __syncthreads();
        if (i == j) {
            Ms[i * HD + t] = s * a;
        } else {
            Ms[i * HD + t] = c * a - s * b;
            Ms[j * HD + t] = s * a + c * b;
        }
        __syncthreads();
    }
    for (int d = 0; d < HD; d++) g_M[d * HD + t] = Ms[d * HD + t];
}

// ---------------------------------------------------------------------------
// Setup kernel 2: sin/cos table, table[s*32+n] = sin/cos(s * inv_freq[n])
// ---------------------------------------------------------------------------
__global__ void build_trig_kernel(const float* __restrict__ inv_freq) {
    const int id = blockIdx.x * blockDim.x + threadIdx.x;  // 65536
    const int s = id >> 5;
    const int n = id & 31;
    const float ang = (float)s * inv_freq[n];
    float sv, cv;
    sincosf(ang, &sv, &cv);
    g_sin[id] = sv;
    g_cos[id] = cv;
}

// ---------------------------------------------------------------------------
// Packed f32x2 FMA (Blackwell sm_100+): two fp32 FMAs per instruction
// ---------------------------------------------------------------------------
__device__ __forceinline__ unsigned long long fma_f32x2(unsigned long long a,
                                                        unsigned long long b,
                                                        unsigned long long c) {
    unsigned long long d;
    asm("fma.rn.f32x2 %0, %1, %2, %3;" : "=l"(d) : "l"(a), "l"(b), "l"(c));
    return d;
}

// ---------------------------------------------------------------------------
// Main kernel: one row (one head-vector of 64 floats) per thread.
// w = v @ M via f32x2 packed FMAs (M broadcast from smem), then RoPE epilogue.
// Block = 128 threads = 128 consecutive rows = 8 consecutive positions.
// ---------------------------------------------------------------------------
__global__ void __launch_bounds__(128, 4)
rotary_main_kernel(const float* __restrict__ x, float* __restrict__ out) {
    __shared__ __align__(16) float MS[HD * HD];   // 16 KB
    __shared__ float SS[8][NROT];
    __shared__ float CS[8][NROT];

    const int t = threadIdx.x;
    const long long base = (long long)blockIdx.x * (128LL * HD);

    // Load M into shared (float4 coalesced)
    for (int i = t; i < (HD * HD) / 4; i += 128)
        ((float4*)MS)[i] = ((const float4*)g_M)[i];

    // Load this block's 8 positions worth of sin/cos
    {
        const int s0 = (blockIdx.x * 8) & (NSEQ - 1);
        for (int i = t; i < 8 * NROT; i += 128) {
            const int ls = i >> 5, n = i & 31;
            SS[ls][n] = g_sin[(s0 + ls) * NROT + n];
            CS[ls][n] = g_cos[(s0 + ls) * NROT + n];
        }
    }
    __syncthreads();

    // 32 packed accumulators: acc[p] = (w[2p], w[2p+1])
    unsigned long long acc[NROT];
#pragma unroll
    for (int p = 0; p < NROT; p++) acc[p] = 0ull;

    const float4* xrow = (const float4*)(x + base) + t * 16;
    const ulonglong2* Mp = (const ulonglong2*)MS;  // 16 ulonglong2 per M-row

#pragma unroll 2
    for (int i = 0; i < 16; i++) {
        const float4 v = xrow[i];
#pragma unroll
        for (int dd = 0; dd < 4; dd++) {
            const float vd = (dd == 0) ? v.x : (dd == 1) ? v.y : (dd == 2) ? v.z : v.w;
            unsigned long long vv;
            asm("mov.b64 %0, {%1, %1};" : "=l"(vv) : "f"(vd));
            const ulonglong2* mrow = Mp + (i * 4 + dd) * 16;
#pragma unroll
            for (int q = 0; q < 16; q++) {
                const ulonglong2 m = mrow[q];   // uniform address -> smem broadcast
                acc[2 * q]     = fma_f32x2(vv, m.x, acc[2 * q]);
                acc[2 * q + 1] = fma_f32x2(vv, m.y, acc[2 * q + 1]);
            }
        }
    }

    // RoPE epilogue + scale by sqrt(1024)=32.
    //   out[p]    = (w[2p]*cos_p - w[2p+1]*sin_p) * 32
    //   out[p+32] = (w[2p]*sin_p + w[2p+1]*cos_p) * 32
    const int ls = t >> 4;  // position slot within block (16 heads per position)
    float4* orow = (float4*)(out + base) + t * 16;
#pragma unroll
    for (int q = 0; q < 8; q++) {
        float lo[4], hi[4];
#pragma unroll
        for (int u = 0; u < 4; u++) {
            const int p = 4 * q + u;
            float a, b;
            asm("mov.b64 {%0, %1}, %2;" : "=f"(a), "=f"(b) : "l"(acc[p]));
            const float c = CS[ls][p];
            const float s = SS[ls][p];
            lo[u] = (a * c - b * s) * 32.0f;
            hi[u] = (a * s + b * c) * 32.0f;
        }
        orow[q]     = make_float4(lo[0], lo[1], lo[2], lo[3]);
        orow[q + 8] = make_float4(hi[0], hi[1], hi[2], hi[3]);
    }
}

// ---------------------------------------------------------------------------
// kernel_launch: inputs in metadata order:
//   0: x (f32, 8388608)  1: thetas (f32,32)  2: theta_scale (f32,1)
//   3: r_matrix (f32,4096)  4: inv_freq (f32,32)  5: pairs (i32,64)
// ---------------------------------------------------------------------------
extern "C" void kernel_launch(void* const* d_in, const int* in_sizes, int n_in,
                              void* d_out, int out_size) {
    const float* x        = (const float*)d_in[0];
    const float* thetas   = (const float*)d_in[1];
    const float* tscale   = (const float*)d_in[2];
    const float* R        = (const float*)d_in[3];
    const float* inv_freq = (const float*)d_in[4];
    const int*   pairs    = (const int*)d_in[5];
    float* out = (float*)d_out;

    build_M_kernel<<<1, 64>>>(thetas, tscale, R, pairs);
    build_trig_kernel<<<64, 1024>>>(inv_freq);
    rotary_main_kernel<<<NROWS / 128, 128>>>(x, out);
}